// round 11
// baseline (speedup 1.0000x reference)
#include <cuda_runtime.h>
#include <math.h>

// Problem constants (fixed by the reference setup)
#define BB   256      // batch
#define CC   3        // channels
#define HWD  16384    // H*W = 128*128
#define NST  5        // states evaluated: s0 + 4 candidates
#define NCL  10       // classes
#define NQ   5        // class pairs (NCL/2)
#define NPL  (CC * NQ)    // 15 W planes
#define PAIRS (HWD / 2)   // 8192 pixel pairs per plane

// Tiling
#define BG      8             // batches per block (8 warps, 256 threads)
#define NGRP    (BB / BG)     // 32 batch groups
#define SLOTS   9             // pixel slots: 9*32 = 288 blocks ~ 2/SM wave
#define CH      32            // pairs per chunk (1 compute iter per warp)
#define NCHUNK  (PAIRS / CH)  // 256 chunks total
#define STAGES  3             // per-warp pipeline depth

typedef unsigned long long u64;

// Scratch (static device arrays: allocation-free)
__device__ ulonglong2 g_Wp[NPL * PAIRS];    // packed W: [plane][pair]
// Layout: [slot][state][class][batch] -> final_kernel loads coalesced in b
__device__ float g_partial[SLOTS * NST * NCL * BB];

// ---------------------------------------------------------------------------
// f32x2 packed-math + async helpers (sm_100+)
// ---------------------------------------------------------------------------
__device__ __forceinline__ u64 pack2(float lo, float hi) {
    u64 r; asm("mov.b64 %0, {%1, %2};" : "=l"(r) : "f"(lo), "f"(hi)); return r;
}
__device__ __forceinline__ u64 fma2(u64 a, u64 b, u64 c) {
    u64 d; asm("fma.rn.f32x2 %0, %1, %2, %3;" : "=l"(d) : "l"(a), "l"(b), "l"(c)); return d;
}
__device__ __forceinline__ u64 mul2(u64 a, u64 b) {
    u64 d; asm("mul.rn.f32x2 %0, %1, %2;" : "=l"(d) : "l"(a), "l"(b)); return d;
}
__device__ __forceinline__ u64 add2(u64 a, u64 b) {
    u64 d; asm("add.rn.f32x2 %0, %1, %2;" : "=l"(d) : "l"(a), "l"(b)); return d;
}
__device__ __forceinline__ void unpack2(u64 v, float& lo, float& hi) {
    asm("mov.b64 {%0, %1}, %2;" : "=f"(lo), "=f"(hi) : "l"(v));
}
__device__ __forceinline__ u64 msel(bool c) {
    return c ? 0x3f8000003f800000ULL : 0ULL;
}
__device__ __forceinline__ unsigned smem_u32(const void* p) {
    return (unsigned)__cvta_generic_to_shared(p);
}
__device__ __forceinline__ void cp_async16(unsigned dst, const void* src) {
    asm volatile("cp.async.cg.shared.global [%0], [%1], 16;"
                 :: "r"(dst), "l"(src) : "memory");
}
__device__ __forceinline__ void cp_commit() {
    asm volatile("cp.async.commit_group;" ::: "memory");
}
template <int N>
__device__ __forceinline__ void cp_wait() {
    asm volatile("cp.async.wait_group %0;" :: "n"(N) : "memory");
}

// ---------------------------------------------------------------------------
// K0: repack W [CC*HWD, NCL] -> g_Wp [c][q][pixel] class-pair stream
// ---------------------------------------------------------------------------
__global__ void prep_kernel(const float* __restrict__ W)
{
    int r = blockIdx.x * blockDim.x + threadIdx.x;   // r in [0, CC*HWD)
    if (r < CC * HWD) {
        int c = r / HWD;
        int p = r - c * HWD;
        const float2* Wr = reinterpret_cast<const float2*>(W + (size_t)r * NCL); // 8B-aligned rows
        float2* wp2 = reinterpret_cast<float2*>(g_Wp);
#pragma unroll
        for (int q = 0; q < NQ; q++)
            wp2[(c * NQ + q) * HWD + p] = Wr[q];
    }
}

// ---------------------------------------------------------------------------
// K1: per-warp private cp.async input pipeline (depth 3, NO block barriers)
// + mask generation + 5-state masked partial sums. W via __ldg (L1/L2).
// Grid (SLOTS, NGRP), 256 threads; warp w = batch blockIdx.y*8 + w.
// ---------------------------------------------------------------------------
__global__ __launch_bounds__(BG * 32, 2)
void main_kernel(const float* __restrict__ zl,
                 const float* __restrict__ x,
                 const float* __restrict__ bern)
{
    // per-warp: STAGES stages x 8 streams x 32 pairs (float2) = 2KB/stage
    __shared__ float2 sIn[BG * STAGES * 8 * 32];   // 49,152 B

    const int tid  = threadIdx.x;
    const int warp = tid >> 5;
    const int lane = tid & 31;
    const int bat  = blockIdx.y * BG + warp;
    const int s    = blockIdx.x;

    const int lo_c = (s * NCHUNK) / SLOTS;
    const int hi_c = ((s + 1) * NCHUNK) / SLOTS;
    const int nch  = hi_c - lo_c;

    // ---- Per-lane staging descriptors: 4 x 16B units of this warp's streams.
    // unit u in [0,128): stream = u>>4, pp = u&15 (covers pairs 2pp, 2pp+1)
    const float2* src[4];
    unsigned      dst[4];
#pragma unroll
    for (int j = 0; j < 4; j++) {
        int u  = lane + j * 32;
        int st = u >> 4;
        int pp = u & 15;
        const float2* base;
        if (st == 0)       base = reinterpret_cast<const float2*>(zl)   + bat * PAIRS;
        else if (st <= 3)  base = reinterpret_cast<const float2*>(x)    + (bat * CC + (st - 1)) * PAIRS;
        else               base = reinterpret_cast<const float2*>(bern) + ((st - 4) * BB + bat) * PAIRS;
        src[j] = base + 2 * pp;
        dst[j] = smem_u32(&sIn[(warp * STAGES) * 256 + st * 32 + 2 * pp]);
    }

    // stage i (relative chunk index); ALWAYS commits a group (possibly empty)
    auto stage_g = [&](int i) {
        if (i < nch) {
            const int cb  = (lo_c + i) * CH;          // float2 offset in plane
            const unsigned off = (unsigned)(i % STAGES) * (8 * 32 * 8);  // bytes
#pragma unroll
            for (int j = 0; j < 4; j++)
                cp_async16(dst[j] + off, src[j] + cb);
        }
        cp_commit();
    };

    u64 acc[NST][NQ];
#pragma unroll
    for (int kk = 0; kk < NST; kk++)
#pragma unroll
        for (int q = 0; q < NQ; q++) acc[kk][q] = 0ULL;

    const ulonglong2* wp = g_Wp;

    // ---- Pipeline: prologue 3 stages, then wait/compute/stage-ahead
    stage_g(0); stage_g(1); stage_g(2);
    for (int i = 0; i < nch; i++) {
        cp_wait<2>();        // groups 0..i complete (2 newest may be in flight)
        __syncwarp();

        const float2* inb = sIn + (warp * STAGES + (i % STAGES)) * 256;
        float2 z  = inb[0 * 32 + lane];
        float2 a0 = inb[1 * 32 + lane];
        float2 a1 = inb[2 * 32 + lane];
        float2 a2 = inb[3 * 32 + lane];
        float2 c0 = inb[4 * 32 + lane];
        float2 c1 = inb[5 * 32 + lane];
        float2 c2 = inb[6 * 32 + lane];
        float2 c3 = inb[7 * 32 + lane];

        float zp0 = 1.0f / (1.0f + __expf(-z.x));
        float zp1 = 1.0f / (1.0f + __expf(-z.y));

        u64 mA[NST], mB[NST];
        mA[0] = msel(z.x >= 0.0f);  mB[0] = msel(z.y >= 0.0f);
        mA[1] = msel(c0.x < zp0);   mB[1] = msel(c0.y < zp1);
        mA[2] = msel(c1.x < zp0);   mB[2] = msel(c1.y < zp1);
        mA[3] = msel(c2.x < zp0);   mB[3] = msel(c2.y < zp1);
        mA[4] = msel(c3.x < zp0);   mB[4] = msel(c3.y < zp1);

        u64 xb0 = pack2(a0.x, a0.x);
        u64 xb1 = pack2(a1.x, a1.x);
        u64 xb2 = pack2(a2.x, a2.x);
        u64 yb0 = pack2(a0.y, a0.y);
        u64 yb1 = pack2(a1.y, a1.y);
        u64 yb2 = pack2(a2.y, a2.y);

        const int t = (lo_c + i) * CH + lane;
#pragma unroll
        for (int q = 0; q < NQ; q++) {
            ulonglong2 w0 = __ldg(wp + (0 * NQ + q) * PAIRS + t);
            ulonglong2 w1 = __ldg(wp + (1 * NQ + q) * PAIRS + t);
            ulonglong2 w2 = __ldg(wp + (2 * NQ + q) * PAIRS + t);

            u64 v0 = fma2(xb2, w2.x, fma2(xb1, w1.x, mul2(xb0, w0.x)));
            u64 v1 = fma2(yb2, w2.y, fma2(yb1, w1.y, mul2(yb0, w0.y)));

#pragma unroll
            for (int kk = 0; kk < NST; kk++) {
                acc[kk][q] = fma2(mA[kk], v0, acc[kk][q]);
                acc[kk][q] = fma2(mB[kk], v1, acc[kk][q]);
            }
        }

        stage_g(i + 3);      // refill the buffer compute(i) just consumed
    }

    // warp butterfly reduce (each warp = one batch), packed adds
#pragma unroll
    for (int kk = 0; kk < NST; kk++)
#pragma unroll
        for (int q = 0; q < NQ; q++) {
            u64 v = acc[kk][q];
#pragma unroll
            for (int off = 16; off > 0; off >>= 1)
                v = add2(v, __shfl_xor_sync(0xffffffffu, v, off));
            acc[kk][q] = v;
        }

    if (lane == 0) {
#pragma unroll
        for (int kk = 0; kk < NST; kk++)
#pragma unroll
            for (int q = 0; q < NQ; q++) {
                float flo, fhi;
                unpack2(acc[kk][q], flo, fhi);
                // transposed layout: [slot][state][class][batch]
                float* dstp = &g_partial[((s * NST + kk) * NCL) * BB + bat];
                dstp[(2 * q) * BB]     = flo;
                dstp[(2 * q + 1) * BB] = fhi;
            }
    }
}

// ---------------------------------------------------------------------------
// K2: sum slot partials (coalesced in b), log-softmax -> pz, MH chain,
// select, write output. 8 blocks x 32 threads (one thread per batch).
// ---------------------------------------------------------------------------
__global__ void final_kernel(const int* __restrict__ y,
                             const float* __restrict__ u,
                             const float* __restrict__ bias,
                             float* __restrict__ out)
{
    int b = blockIdx.x * blockDim.x + threadIdx.x;
    if (b >= BB) return;

    float logits[NST][NCL];
#pragma unroll
    for (int kk = 0; kk < NST; kk++)
#pragma unroll
        for (int n = 0; n < NCL; n++) {
            float sacc = 0.0f;
#pragma unroll
            for (int sc = 0; sc < SLOTS; sc++)
                sacc += g_partial[((sc * NST + kk) * NCL + n) * BB + b];
            logits[kk][n] = sacc + bias[n];
        }

    int yb = y[b];
    float pz[NST];
#pragma unroll
    for (int kk = 0; kk < NST; kk++) {
        float mx = logits[kk][0];
#pragma unroll
        for (int n = 1; n < NCL; n++) mx = fmaxf(mx, logits[kk][n]);
        float se = 0.0f;
#pragma unroll
        for (int n = 0; n < NCL; n++) se += expf(logits[kk][n] - mx);
        float lse = mx + logf(se);
        float ly = logits[kk][0];
#pragma unroll
        for (int n = 0; n < NCL; n++) if (n == yb) ly = logits[kk][n];
        pz[kk] = ly - lse;
    }

    // MH chain: accept when log(u) <= pz_cand - lp
    int sel = 0;
    float lp = pz[0];
#pragma unroll
    for (int k = 1; k < NST; k++) {
        float lu = logf(u[(k - 1) * BB + b]);
        if (lu <= pz[k] - lp) { sel = k; lp = pz[k]; }
    }

#pragma unroll
    for (int n = 0; n < NCL; n++) {
        float v = logits[0][n];
#pragma unroll
        for (int kk = 1; kk < NST; kk++) if (kk == sel) v = logits[kk][n];
        out[b * NCL + n] = v;
    }
}

// ---------------------------------------------------------------------------
extern "C" void kernel_launch(void* const* d_in, const int* in_sizes, int n_in,
                              void* d_out, int out_size)
{
    const float* zl   = (const float*)d_in[0];   // [256,1,128,128]
    const float* x    = (const float*)d_in[1];   // [256,3,128,128]
    const int*   y    = (const int*)  d_in[2];   // [256]
    const float* bern = (const float*)d_in[3];   // [4,256,1,128,128]
    const float* u    = (const float*)d_in[4];   // [4,256]
    const float* W    = (const float*)d_in[5];   // [49152,10]
    const float* bias = (const float*)d_in[6];   // [10]
    float* out = (float*)d_out;                  // [256,10]

    prep_kernel<<<(CC * HWD + 255) / 256, 256>>>(W);

    dim3 grid(SLOTS, NGRP);
    main_kernel<<<grid, BG * 32>>>(zl, x, bern);

    final_kernel<<<BB / 32, 32>>>(y, u, bias, out);
}

// round 12
// speedup vs baseline: 1.3200x; 1.3200x over previous
#include <cuda_runtime.h>
#include <math.h>

// Problem constants (fixed by the reference setup)
#define BB   256      // batch
#define CC   3        // channels
#define HWD  16384    // H*W = 128*128
#define NST  5        // states evaluated: s0 + 4 candidates
#define NCL  10       // classes
#define NQ   5        // class pairs (NCL/2)
#define NPL  (CC * NQ)    // 15 W planes
#define PAIRS (HWD / 2)   // 8192 pixel pairs per plane

// Tiling
#define BG      4             // batches per block (4 warps, 128 threads)
#define NGRP    (BB / BG)     // 64 batch groups
#define SLOTS   9             // pixel slots: 9*64 = 576 blocks ~ one 4/SM wave
#define CH      32            // pairs per chunk (1 compute iter per warp)
#define NCHUNK  (PAIRS / CH)  // 256 chunks total
#define STAGES  3             // pipeline depth
#define SWSTRIDE 33           // padded W plane stride (ulonglong2)
#define IN_STAGE_F2 (BG * 8 * CH)     // 1024 float2 (8 KB) per input stage
#define W_STAGE_U2  (NPL * SWSTRIDE)  // 495 ulonglong2 (7.92 KB) per W stage
#define W_UNITS     (NPL * CH)        // 480 16B units per W chunk

typedef unsigned long long u64;

// Scratch (static device arrays: allocation-free)
__device__ ulonglong2 g_Wp[NPL * PAIRS];    // packed W: [plane][pair]
// Layout: [slot][state][class][batch] -> final_kernel loads coalesced in b
__device__ float g_partial[SLOTS * NST * NCL * BB];

// ---------------------------------------------------------------------------
// f32x2 packed-math + async helpers (sm_100+)
// ---------------------------------------------------------------------------
__device__ __forceinline__ u64 pack2(float lo, float hi) {
    u64 r; asm("mov.b64 %0, {%1, %2};" : "=l"(r) : "f"(lo), "f"(hi)); return r;
}
__device__ __forceinline__ u64 fma2(u64 a, u64 b, u64 c) {
    u64 d; asm("fma.rn.f32x2 %0, %1, %2, %3;" : "=l"(d) : "l"(a), "l"(b), "l"(c)); return d;
}
__device__ __forceinline__ u64 mul2(u64 a, u64 b) {
    u64 d; asm("mul.rn.f32x2 %0, %1, %2;" : "=l"(d) : "l"(a), "l"(b)); return d;
}
__device__ __forceinline__ u64 add2(u64 a, u64 b) {
    u64 d; asm("add.rn.f32x2 %0, %1, %2;" : "=l"(d) : "l"(a), "l"(b)); return d;
}
__device__ __forceinline__ void unpack2(u64 v, float& lo, float& hi) {
    asm("mov.b64 {%0, %1}, %2;" : "=f"(lo), "=f"(hi) : "l"(v));
}
__device__ __forceinline__ u64 msel(bool c) {
    return c ? 0x3f8000003f800000ULL : 0ULL;
}
__device__ __forceinline__ unsigned smem_u32(const void* p) {
    return (unsigned)__cvta_generic_to_shared(p);
}
__device__ __forceinline__ void cp_async16(unsigned dst, const void* src) {
    asm volatile("cp.async.cg.shared.global [%0], [%1], 16;"
                 :: "r"(dst), "l"(src) : "memory");
}
__device__ __forceinline__ void cp_commit() {
    asm volatile("cp.async.commit_group;" ::: "memory");
}
template <int N>
__device__ __forceinline__ void cp_wait() {
    asm volatile("cp.async.wait_group %0;" :: "n"(N) : "memory");
}

// ---------------------------------------------------------------------------
// K0: repack W [CC*HWD, NCL] -> g_Wp [c][q][pixel] class-pair stream
// ---------------------------------------------------------------------------
__global__ void prep_kernel(const float* __restrict__ W)
{
    int r = blockIdx.x * blockDim.x + threadIdx.x;   // r in [0, CC*HWD)
    if (r < CC * HWD) {
        int c = r / HWD;
        int p = r - c * HWD;
        const float2* Wr = reinterpret_cast<const float2*>(W + (size_t)r * NCL); // 8B-aligned rows
        float2* wp2 = reinterpret_cast<float2*>(g_Wp);
#pragma unroll
        for (int q = 0; q < NQ; q++)
            wp2[(c * NQ + q) * HWD + p] = Wr[q];
    }
}

// ---------------------------------------------------------------------------
// K1: depth-3 block-wide cp.async pipeline (inputs + W, all smem) + mask
// generation + 5-state masked partial sums.
// Grid (SLOTS, NGRP), 128 threads, 4 blocks/SM.
// Iter: wait<2> -> sync -> compute(i) -> sync -> stage(i+3).
// ---------------------------------------------------------------------------
__global__ __launch_bounds__(BG * 32, 4)
void main_kernel(const float* __restrict__ zl,
                 const float* __restrict__ x,
                 const float* __restrict__ bern)
{
    __shared__ float2     sIn[STAGES * IN_STAGE_F2];  // 24,576 B
    __shared__ ulonglong2 sW [STAGES * W_STAGE_U2];   // 23,760 B  (48,336 total)

    const int tid  = threadIdx.x;
    const int warp = tid >> 5;
    const int lane = tid & 31;
    const int bat  = blockIdx.y * BG + warp;
    const int s    = blockIdx.x;

    const int lo_c = (s * NCHUNK) / SLOTS;
    const int hi_c = ((s + 1) * NCHUNK) / SLOTS;
    const int nch  = hi_c - lo_c;

    // ---- Per-thread staging descriptors
    // input unit u in [0,512): b = u>>7, stream = (u>>4)&7, pp = u&15 (2 pairs)
    const float2* inSrc[4];
    unsigned      inDst[4];
#pragma unroll
    for (int j = 0; j < 4; j++) {
        int u  = tid + j * 128;
        int b  = blockIdx.y * BG + (u >> 7);
        int st = (u >> 4) & 7;
        int pp = u & 15;
        const float2* base;
        if (st == 0)       base = reinterpret_cast<const float2*>(zl)   + b * PAIRS;
        else if (st <= 3)  base = reinterpret_cast<const float2*>(x)    + (b * CC + (st - 1)) * PAIRS;
        else               base = reinterpret_cast<const float2*>(bern) + ((st - 4) * BB + b) * PAIRS;
        inSrc[j] = base + 2 * pp;
        inDst[j] = smem_u32(&sIn[((u >> 7) * 8 + st) * CH + 2 * pp]);
    }
    // W unit w in [0,480): plane = w>>5, k = w&31
    const ulonglong2* wSrc[4];
    unsigned          wDst[4];
    bool              wOk[4];
#pragma unroll
    for (int j = 0; j < 4; j++) {
        int w = tid + j * 128;
        wOk[j]  = (w < W_UNITS);
        int pl  = w >> 5, k = w & 31;
        wSrc[j] = g_Wp + pl * PAIRS + k;
        wDst[j] = smem_u32(&sW[pl * SWSTRIDE + k]);
    }

    // stage chunk i (relative); ALWAYS commits a group (possibly empty)
    auto stage_g = [&](int i) {
        if (i < nch) {
            const int cb = (lo_c + i) * CH;                      // pair offset
            const unsigned inOff = (unsigned)(i % STAGES) * (IN_STAGE_F2 * 8);
            const unsigned wOff  = (unsigned)(i % STAGES) * (W_STAGE_U2 * 16);
#pragma unroll
            for (int j = 0; j < 4; j++)
                cp_async16(inDst[j] + inOff, inSrc[j] + cb);
#pragma unroll
            for (int j = 0; j < 4; j++)
                if (wOk[j]) cp_async16(wDst[j] + wOff, wSrc[j] + cb);
        }
        cp_commit();
    };

    u64 acc[NST][NQ];
#pragma unroll
    for (int kk = 0; kk < NST; kk++)
#pragma unroll
        for (int q = 0; q < NQ; q++) acc[kk][q] = 0ULL;

    // ---- Pipeline
    stage_g(0); stage_g(1); stage_g(2);
    for (int i = 0; i < nch; i++) {
        cp_wait<2>();       // group i complete; i+1, i+2 in flight
        __syncthreads();    // data visible to all threads

        const int buf = i % STAGES;
        const float2* inb = sIn + buf * IN_STAGE_F2 + warp * (8 * CH);
        float2 z  = inb[0 * CH + lane];
        float2 a0 = inb[1 * CH + lane];
        float2 a1 = inb[2 * CH + lane];
        float2 a2 = inb[3 * CH + lane];
        float2 c0 = inb[4 * CH + lane];
        float2 c1 = inb[5 * CH + lane];
        float2 c2 = inb[6 * CH + lane];
        float2 c3 = inb[7 * CH + lane];

        float zp0 = 1.0f / (1.0f + __expf(-z.x));
        float zp1 = 1.0f / (1.0f + __expf(-z.y));

        u64 mA[NST], mB[NST];
        mA[0] = msel(z.x >= 0.0f);  mB[0] = msel(z.y >= 0.0f);
        mA[1] = msel(c0.x < zp0);   mB[1] = msel(c0.y < zp1);
        mA[2] = msel(c1.x < zp0);   mB[2] = msel(c1.y < zp1);
        mA[3] = msel(c2.x < zp0);   mB[3] = msel(c2.y < zp1);
        mA[4] = msel(c3.x < zp0);   mB[4] = msel(c3.y < zp1);

        u64 xb0 = pack2(a0.x, a0.x);
        u64 xb1 = pack2(a1.x, a1.x);
        u64 xb2 = pack2(a2.x, a2.x);
        u64 yb0 = pack2(a0.y, a0.y);
        u64 yb1 = pack2(a1.y, a1.y);
        u64 yb2 = pack2(a2.y, a2.y);

        const ulonglong2* wb = sW + buf * W_STAGE_U2;
#pragma unroll
        for (int q = 0; q < NQ; q++) {
            ulonglong2 w0 = wb[(0 * NQ + q) * SWSTRIDE + lane];
            ulonglong2 w1 = wb[(1 * NQ + q) * SWSTRIDE + lane];
            ulonglong2 w2 = wb[(2 * NQ + q) * SWSTRIDE + lane];

            u64 v0 = fma2(xb2, w2.x, fma2(xb1, w1.x, mul2(xb0, w0.x)));
            u64 v1 = fma2(yb2, w2.y, fma2(yb1, w1.y, mul2(yb0, w0.y)));

#pragma unroll
            for (int kk = 0; kk < NST; kk++) {
                acc[kk][q] = fma2(mA[kk], v0, acc[kk][q]);
                acc[kk][q] = fma2(mB[kk], v1, acc[kk][q]);
            }
        }
        __syncthreads();    // all warps done with buf before it is restaged
        stage_g(i + 3);     // refill the buffer just consumed
    }

    // warp butterfly reduce (each warp = one batch), packed adds
#pragma unroll
    for (int kk = 0; kk < NST; kk++)
#pragma unroll
        for (int q = 0; q < NQ; q++) {
            u64 v = acc[kk][q];
#pragma unroll
            for (int off = 16; off > 0; off >>= 1)
                v = add2(v, __shfl_xor_sync(0xffffffffu, v, off));
            acc[kk][q] = v;
        }

    if (lane == 0) {
#pragma unroll
        for (int kk = 0; kk < NST; kk++)
#pragma unroll
            for (int q = 0; q < NQ; q++) {
                float flo, fhi;
                unpack2(acc[kk][q], flo, fhi);
                // transposed layout: [slot][state][class][batch]
                float* dstp = &g_partial[((s * NST + kk) * NCL) * BB + bat];
                dstp[(2 * q) * BB]     = flo;
                dstp[(2 * q + 1) * BB] = fhi;
            }
    }
}

// ---------------------------------------------------------------------------
// K2: sum slot partials (coalesced in b), log-softmax -> pz, MH chain,
// select, write output. 8 blocks x 32 threads (one thread per batch).
// ---------------------------------------------------------------------------
__global__ void final_kernel(const int* __restrict__ y,
                             const float* __restrict__ u,
                             const float* __restrict__ bias,
                             float* __restrict__ out)
{
    int b = blockIdx.x * blockDim.x + threadIdx.x;
    if (b >= BB) return;

    float logits[NST][NCL];
#pragma unroll
    for (int kk = 0; kk < NST; kk++)
#pragma unroll
        for (int n = 0; n < NCL; n++) {
            float sacc = 0.0f;
#pragma unroll
            for (int sc = 0; sc < SLOTS; sc++)
                sacc += g_partial[((sc * NST + kk) * NCL + n) * BB + b];
            logits[kk][n] = sacc + bias[n];
        }

    int yb = y[b];
    float pz[NST];
#pragma unroll
    for (int kk = 0; kk < NST; kk++) {
        float mx = logits[kk][0];
#pragma unroll
        for (int n = 1; n < NCL; n++) mx = fmaxf(mx, logits[kk][n]);
        float se = 0.0f;
#pragma unroll
        for (int n = 0; n < NCL; n++) se += expf(logits[kk][n] - mx);
        float lse = mx + logf(se);
        float ly = logits[kk][0];
#pragma unroll
        for (int n = 0; n < NCL; n++) if (n == yb) ly = logits[kk][n];
        pz[kk] = ly - lse;
    }

    // MH chain: accept when log(u) <= pz_cand - lp
    int sel = 0;
    float lp = pz[0];
#pragma unroll
    for (int k = 1; k < NST; k++) {
        float lu = logf(u[(k - 1) * BB + b]);
        if (lu <= pz[k] - lp) { sel = k; lp = pz[k]; }
    }

#pragma unroll
    for (int n = 0; n < NCL; n++) {
        float v = logits[0][n];
#pragma unroll
        for (int kk = 1; kk < NST; kk++) if (kk == sel) v = logits[kk][n];
        out[b * NCL + n] = v;
    }
}

// ---------------------------------------------------------------------------
extern "C" void kernel_launch(void* const* d_in, const int* in_sizes, int n_in,
                              void* d_out, int out_size)
{
    const float* zl   = (const float*)d_in[0];   // [256,1,128,128]
    const float* x    = (const float*)d_in[1];   // [256,3,128,128]
    const int*   y    = (const int*)  d_in[2];   // [256]
    const float* bern = (const float*)d_in[3];   // [4,256,1,128,128]
    const float* u    = (const float*)d_in[4];   // [4,256]
    const float* W    = (const float*)d_in[5];   // [49152,10]
    const float* bias = (const float*)d_in[6];   // [10]
    float* out = (float*)d_out;                  // [256,10]

    prep_kernel<<<(CC * HWD + 255) / 256, 256>>>(W);

    dim3 grid(SLOTS, NGRP);
    main_kernel<<<grid, BG * 32>>>(zl, x, bern);

    final_kernel<<<BB / 32, 32>>>(y, u, bias, out);
}